// round 4
// baseline (speedup 1.0000x reference)
#include <cuda_runtime.h>
#include <cstdint>

// ---------------------------------------------------------------------------
// GroupedLinear: out[t, o] = sum_i X[t, i] * W[g(t), o, i]
// G=8 balanced groups, 2048 tokens/group, in=out=2048, fp32.
//
// R3 analysis: SMEM/LDSM-duplication bound (~17 GB crossbar traffic), not
// cvt-bound. This round: warp tile 64x64, CTA tile 128x256 -> bytes/FLOP
// through SMEM down 33%, MMA:LDSM ratio up 2x.
// ---------------------------------------------------------------------------

#define NUM_GROUPS 8
#define IN_F       2048
#define OUT_F      2048
#define TOKENS     16384

// Pre-rounded tf32 copies (device-global scratch: allowed)
__device__ float g_xr[(size_t)TOKENS * IN_F];                 // 128 MB
__device__ float g_wr[(size_t)NUM_GROUPS * OUT_F * IN_F];     // 128 MB

constexpr int BM = 128;
constexpr int BN = 256;
constexpr int BK = 32;                       // 32 fp32 = 128 B rows
constexpr int THREADS = 256;                 // 8 warps: 2 (M) x 4 (N), 64x64 each
constexpr int STAGES = 3;
constexpr int KITERS = IN_F / BK;            // 64
constexpr int A_BYTES = BM * BK * 4;         // 16 KB
constexpr int B_BYTES = BN * BK * 4;         // 32 KB
constexpr int STAGE_BYTES = A_BYTES + B_BYTES;   // 48 KB
constexpr int SMEM_TOTAL = STAGES * STAGE_BYTES; // 144 KB

// ---------------------------------------------------------------------------
// PTX helpers (baseline PTX only — harness ptxas targets plain sm_103)
// ---------------------------------------------------------------------------
__device__ __forceinline__ uint32_t smem_u32(const void* p) {
    uint32_t a;
    asm("{ .reg .u64 t; cvta.to.shared.u64 t, %1; cvt.u32.u64 %0, t; }"
        : "=r"(a) : "l"(p));
    return a;
}

// SW128 swizzle: XOR row bits [9:7] into 16B-chunk bits [6:4]
__device__ __forceinline__ uint32_t swz(uint32_t o) {
    return o ^ ((o >> 3) & 0x70);
}

__device__ __forceinline__ void cp16(uint32_t dst, const void* src) {
    asm volatile("cp.async.cg.shared.global [%0], [%1], 16;"
                 :: "r"(dst), "l"(src));
}
__device__ __forceinline__ void cp_commit() {
    asm volatile("cp.async.commit_group;");
}
template <int N>
__device__ __forceinline__ void cp_wait() {
    asm volatile("cp.async.wait_group %0;" :: "n"(N));
}

__device__ __forceinline__ void ldsm4(uint32_t* r, uint32_t addr) {
    asm volatile("ldmatrix.sync.aligned.m8n8.x4.shared.b16 {%0,%1,%2,%3}, [%4];"
                 : "=r"(r[0]), "=r"(r[1]), "=r"(r[2]), "=r"(r[3]) : "r"(addr));
}

__device__ __forceinline__ void mma_tf32(float* c, const uint32_t* a,
                                         uint32_t b0, uint32_t b1) {
    asm volatile(
        "mma.sync.aligned.m16n8k8.row.col.f32.tf32.tf32.f32 "
        "{%0,%1,%2,%3}, {%4,%5,%6,%7}, {%8,%9}, {%0,%1,%2,%3};"
        : "+f"(c[0]), "+f"(c[1]), "+f"(c[2]), "+f"(c[3])
        : "r"(a[0]), "r"(a[1]), "r"(a[2]), "r"(a[3]), "r"(b0), "r"(b1));
}

// ---------------------------------------------------------------------------
// Pre-pass: fp32 -> round-to-nearest tf32 copy (removes HW truncation bias
// without any mainloop cvt instructions)
// ---------------------------------------------------------------------------
__global__ void __launch_bounds__(256) round_tf32_kernel(
    const float4* __restrict__ in, float4* __restrict__ out, int n4) {
    int i = blockIdx.x * blockDim.x + threadIdx.x;
    if (i >= n4) return;
    float4 v = in[i];
    uint4 o;
    asm("cvt.rna.tf32.f32 %0, %1;" : "=r"(o.x) : "f"(v.x));
    asm("cvt.rna.tf32.f32 %0, %1;" : "=r"(o.y) : "f"(v.y));
    asm("cvt.rna.tf32.f32 %0, %1;" : "=r"(o.z) : "f"(v.z));
    asm("cvt.rna.tf32.f32 %0, %1;" : "=r"(o.w) : "f"(v.w));
    reinterpret_cast<uint4*>(out)[i] = o;
}

// ---------------------------------------------------------------------------
// Stage loader: A (1024 chunks) + B (2048 chunks), 12 x 16B per thread
// ---------------------------------------------------------------------------
__device__ __forceinline__ void load_stage(uint32_t sb, int stage,
                                           const float* __restrict__ Ag,
                                           const float* __restrict__ Bg,
                                           int k0, int tid) {
    const uint32_t sA = sb + stage * STAGE_BYTES;
    const uint32_t sB = sA + A_BYTES;
    #pragma unroll
    for (int i = 0; i < 4; ++i) {                // A: 128 rows x 8 chunks
        const int c   = tid + THREADS * i;
        const int row = c >> 3;
        const int cc  = c & 7;
        const uint32_t d = swz((uint32_t)(row * 128 + cc * 16));
        cp16(sA + d, Ag + (size_t)row * IN_F + k0 + cc * 4);
    }
    #pragma unroll
    for (int i = 0; i < 8; ++i) {                // B: 256 rows x 8 chunks
        const int c   = tid + THREADS * i;
        const int row = c >> 3;
        const int cc  = c & 7;
        const uint32_t d = swz((uint32_t)(row * 128 + cc * 16));
        cp16(sB + d, Bg + (size_t)row * IN_F + k0 + cc * 4);
    }
}

// ---------------------------------------------------------------------------
// Kernel: one 128x256 output tile per CTA. Warp tile 64(M) x 64(N).
// Mainloop per k8 per warp: 8 LDSM.x4 + 32 HMMA, zero cvt.
// ---------------------------------------------------------------------------
__global__ void __launch_bounds__(THREADS, 1)
grouped_gemm_tf32(const float* __restrict__ X, const float* __restrict__ W,
                  float* __restrict__ out) {
    extern __shared__ __align__(1024) char smem[];
    const uint32_t sb = smem_u32(smem);
    const int tid  = threadIdx.x;
    const int lane = tid & 31;
    const int wid  = tid >> 5;
    const int warp_m = wid & 1;    // 0..1 -> 64-row halves
    const int warp_n = wid >> 1;   // 0..3 -> 64-col quarters

    // Tile mapping: groups outermost (L2 weight reuse). 16 mt x 8 nt per group.
    const int b  = blockIdx.x;
    const int g  = b >> 7;
    const int t  = b & 127;
    const int mt = t >> 3;
    const int nt = t & 7;

    const float* Ag = X + (size_t)(g * (TOKENS / NUM_GROUPS) + mt * BM) * IN_F;
    const float* Bg = W + (size_t)(g * OUT_F + nt * BN) * IN_F;

    // acc[i][j]: m16 tile i (4), n8 tile j (8)
    float acc[4][8][4];
    #pragma unroll
    for (int i = 0; i < 4; ++i)
        #pragma unroll
        for (int j = 0; j < 8; ++j)
            #pragma unroll
            for (int r = 0; r < 4; ++r) acc[i][j][r] = 0.0f;

    // ldmatrix base offsets (k8 slice ks applied by XOR with ks*32; k bits
    // [5:6] are disjoint from base low bits and from the swizzle mask's
    // source bits).
    uint32_t a_off[4];
    #pragma unroll
    for (int i = 0; i < 4; ++i)
        a_off[i] = swz((uint32_t)(
            (warp_m * 64 + i * 16 + (lane & 15)) * 128 + (lane & 16)));
    uint32_t b_off[2][2];   // [32-col half][kc half]
    #pragma unroll
    for (int h = 0; h < 2; ++h) {
        b_off[h][0] = swz((uint32_t)((warp_n * 64 + h * 32 + lane) * 128));
        b_off[h][1] = swz((uint32_t)((warp_n * 64 + h * 32 + lane) * 128 + 16));
    }

    // Prologue: fill first STAGES-1 stages
    load_stage(sb, 0, Ag, Bg, 0, tid);
    cp_commit();
    load_stage(sb, 1, Ag, Bg, BK, tid);
    cp_commit();

    for (int kit = 0; kit < KITERS; ++kit) {
        if (kit < KITERS - 1) cp_wait<1>(); else cp_wait<0>();
        __syncthreads();

        if (kit + 2 < KITERS) {
            load_stage(sb, (kit + 2) % STAGES, Ag, Bg, (kit + 2) * BK, tid);
            cp_commit();
        }

        const uint32_t sA = sb + (kit % STAGES) * STAGE_BYTES;
        const uint32_t sB = sA + A_BYTES;

        #pragma unroll
        for (int ks = 0; ks < 4; ++ks) {          // 4 x k8 steps per BK=32
            const uint32_t kx = (uint32_t)(ks * 32);

            uint32_t a[4][4];
            #pragma unroll
            for (int i = 0; i < 4; ++i)
                ldsm4(a[i], sA + (a_off[i] ^ kx));

            // b frags: [half h][n-octet jj] -> kc0 and kc1 regs
            uint32_t b0[2][4], b1[2][4];
            #pragma unroll
            for (int h = 0; h < 2; ++h) {
                ldsm4(b0[h], sB + (b_off[h][0] ^ kx));
                ldsm4(b1[h], sB + (b_off[h][1] ^ kx));
            }

            #pragma unroll
            for (int i = 0; i < 4; ++i)
                #pragma unroll
                for (int j = 0; j < 8; ++j)
                    mma_tf32(acc[i][j], a[i], b0[j >> 2][j & 3], b1[j >> 2][j & 3]);
        }
    }

    // Epilogue: m16n8 C frag: thread holds (r=t/4, c=2*(t%4)) pairs at rows r, r+8
    const int m0 = g * (TOKENS / NUM_GROUPS) + mt * BM + warp_m * 64;
    const int n0 = nt * BN + warp_n * 64;
    #pragma unroll
    for (int i = 0; i < 4; ++i) {
        const int r = m0 + i * 16 + (lane >> 2);
        float* p0 = out + (size_t)r * OUT_F + n0 + 2 * (lane & 3);
        float* p1 = p0 + (size_t)8 * OUT_F;
        #pragma unroll
        for (int j = 0; j < 8; ++j) {
            *reinterpret_cast<float2*>(p0 + j * 8) =
                make_float2(acc[i][j][0], acc[i][j][1]);
            *reinterpret_cast<float2*>(p1 + j * 8) =
                make_float2(acc[i][j][2], acc[i][j][3]);
        }
    }
}

// ---------------------------------------------------------------------------
// Host launch
// ---------------------------------------------------------------------------
extern "C" void kernel_launch(void* const* d_in, const int* in_sizes, int n_in,
                              void* d_out, int out_size) {
    const float* x = (const float*)d_in[0];   // [16384, 2048]
    const float* w = (const float*)d_in[1];   // [8, 2048, 2048]
    float* out = (float*)d_out;               // [16384, 2048]

    float* xr = nullptr;
    float* wr = nullptr;
    cudaGetSymbolAddress((void**)&xr, g_xr);
    cudaGetSymbolAddress((void**)&wr, g_wr);

    static bool attr_set = false;
    if (!attr_set) {
        cudaFuncSetAttribute(grouped_gemm_tf32,
                             cudaFuncAttributeMaxDynamicSharedMemorySize,
                             SMEM_TOTAL);
        attr_set = true;
    }

    // Pre-pass: round-to-nearest tf32 copies (X and W)
    const int n4 = (TOKENS * IN_F) / 4;       // 8,388,608 float4 per tensor
    round_tf32_kernel<<<(n4 + 255) / 256, 256>>>((const float4*)x, (float4*)xr, n4);
    round_tf32_kernel<<<(n4 + 255) / 256, 256>>>((const float4*)w, (float4*)wr, n4);

    const int grid = NUM_GROUPS * (TOKENS / NUM_GROUPS / BM) * (OUT_F / BN); // 1024
    grouped_gemm_tf32<<<grid, THREADS, SMEM_TOTAL>>>(xr, wr, out);
}

// round 5
// speedup vs baseline: 1.0427x; 1.0427x over previous
#include <cuda_runtime.h>
#include <cstdint>

// ---------------------------------------------------------------------------
// GroupedLinear: out[t, o] = sum_i X[t, i] * W[g(t), o, i]
// G=8 balanced groups, 2048 tokens/group, in=out=2048, fp32.
//
// R4 analysis: 64x64 warp tiles cut smem traffic below the tensor floor, but
// 1 CTA/SM meant every kit-boundary barrier drained the SM. This round: same
// 64x64 warp tiles in a 128x128 CTA of 4 warps -> 96 KB smem -> 2 CTAs/SM,
// barriers overlap across CTAs.
// ---------------------------------------------------------------------------

#define NUM_GROUPS 8
#define IN_F       2048
#define OUT_F      2048
#define TOKENS     16384

// Pre-rounded tf32 copies (device-global scratch: allowed)
__device__ float g_xr[(size_t)TOKENS * IN_F];                 // 128 MB
__device__ float g_wr[(size_t)NUM_GROUPS * OUT_F * IN_F];     // 128 MB

constexpr int BM = 128;
constexpr int BN = 128;
constexpr int BK = 32;                       // 32 fp32 = 128 B rows
constexpr int THREADS = 128;                 // 4 warps: 2 (M) x 2 (N), 64x64 each
constexpr int STAGES = 3;
constexpr int KITERS = IN_F / BK;            // 64
constexpr int A_BYTES = BM * BK * 4;         // 16 KB
constexpr int B_BYTES = BN * BK * 4;         // 16 KB
constexpr int STAGE_BYTES = A_BYTES + B_BYTES;   // 32 KB
constexpr int SMEM_TOTAL = STAGES * STAGE_BYTES; // 96 KB -> 2 CTAs/SM

// ---------------------------------------------------------------------------
// PTX helpers (baseline PTX only — harness ptxas targets plain sm_103)
// ---------------------------------------------------------------------------
__device__ __forceinline__ uint32_t smem_u32(const void* p) {
    uint32_t a;
    asm("{ .reg .u64 t; cvta.to.shared.u64 t, %1; cvt.u32.u64 %0, t; }"
        : "=r"(a) : "l"(p));
    return a;
}

// SW128 swizzle: XOR row bits [9:7] into 16B-chunk bits [6:4]
__device__ __forceinline__ uint32_t swz(uint32_t o) {
    return o ^ ((o >> 3) & 0x70);
}

__device__ __forceinline__ void cp16(uint32_t dst, const void* src) {
    asm volatile("cp.async.cg.shared.global [%0], [%1], 16;"
                 :: "r"(dst), "l"(src));
}
__device__ __forceinline__ void cp_commit() {
    asm volatile("cp.async.commit_group;");
}
template <int N>
__device__ __forceinline__ void cp_wait() {
    asm volatile("cp.async.wait_group %0;" :: "n"(N));
}

__device__ __forceinline__ void ldsm4(uint32_t* r, uint32_t addr) {
    asm volatile("ldmatrix.sync.aligned.m8n8.x4.shared.b16 {%0,%1,%2,%3}, [%4];"
                 : "=r"(r[0]), "=r"(r[1]), "=r"(r[2]), "=r"(r[3]) : "r"(addr));
}

__device__ __forceinline__ void mma_tf32(float* c, const uint32_t* a,
                                         uint32_t b0, uint32_t b1) {
    asm volatile(
        "mma.sync.aligned.m16n8k8.row.col.f32.tf32.tf32.f32 "
        "{%0,%1,%2,%3}, {%4,%5,%6,%7}, {%8,%9}, {%0,%1,%2,%3};"
        : "+f"(c[0]), "+f"(c[1]), "+f"(c[2]), "+f"(c[3])
        : "r"(a[0]), "r"(a[1]), "r"(a[2]), "r"(a[3]), "r"(b0), "r"(b1));
}

// ---------------------------------------------------------------------------
// Pre-pass: fp32 -> round-to-nearest tf32 copy (removes HW truncation bias
// without any mainloop cvt instructions)
// ---------------------------------------------------------------------------
__global__ void __launch_bounds__(256) round_tf32_kernel(
    const float4* __restrict__ in, float4* __restrict__ out, int n4) {
    int i = blockIdx.x * blockDim.x + threadIdx.x;
    if (i >= n4) return;
    float4 v = in[i];
    uint4 o;
    asm("cvt.rna.tf32.f32 %0, %1;" : "=r"(o.x) : "f"(v.x));
    asm("cvt.rna.tf32.f32 %0, %1;" : "=r"(o.y) : "f"(v.y));
    asm("cvt.rna.tf32.f32 %0, %1;" : "=r"(o.z) : "f"(v.z));
    asm("cvt.rna.tf32.f32 %0, %1;" : "=r"(o.w) : "f"(v.w));
    reinterpret_cast<uint4*>(out)[i] = o;
}

// ---------------------------------------------------------------------------
// Stage loader: A (1024 chunks) + B (1024 chunks), 16 x 16B per thread
// ---------------------------------------------------------------------------
__device__ __forceinline__ void load_stage(uint32_t sb, int stage,
                                           const float* __restrict__ Ag,
                                           const float* __restrict__ Bg,
                                           int k0, int tid) {
    const uint32_t sA = sb + stage * STAGE_BYTES;
    const uint32_t sB = sA + A_BYTES;
    #pragma unroll
    for (int i = 0; i < 8; ++i) {                // A: 128 rows x 8 chunks
        const int c   = tid + THREADS * i;
        const int row = c >> 3;
        const int cc  = c & 7;
        const uint32_t d = swz((uint32_t)(row * 128 + cc * 16));
        cp16(sA + d, Ag + (size_t)row * IN_F + k0 + cc * 4);
    }
    #pragma unroll
    for (int i = 0; i < 8; ++i) {                // B: 128 rows x 8 chunks
        const int c   = tid + THREADS * i;
        const int row = c >> 3;
        const int cc  = c & 7;
        const uint32_t d = swz((uint32_t)(row * 128 + cc * 16));
        cp16(sB + d, Bg + (size_t)row * IN_F + k0 + cc * 4);
    }
}

// ---------------------------------------------------------------------------
// Kernel: one 128x128 output tile per CTA, 4 warps, warp tile 64(M) x 64(N).
// Mainloop per k8 per warp: 8 LDSM.x4 + 32 HMMA, zero cvt.
// ---------------------------------------------------------------------------
__global__ void __launch_bounds__(THREADS, 2)
grouped_gemm_tf32(const float* __restrict__ X, const float* __restrict__ W,
                  float* __restrict__ out) {
    extern __shared__ __align__(1024) char smem[];
    const uint32_t sb = smem_u32(smem);
    const int tid  = threadIdx.x;
    const int lane = tid & 31;
    const int wid  = tid >> 5;
    const int warp_m = wid & 1;    // 0..1 -> 64-row halves
    const int warp_n = wid >> 1;   // 0..1 -> 64-col halves

    // Tile mapping: groups outermost (L2 weight reuse). 16 mt x 16 nt per group.
    const int b  = blockIdx.x;
    const int g  = b >> 8;
    const int t  = b & 255;
    const int mt = t >> 4;
    const int nt = t & 15;

    const float* Ag = X + (size_t)(g * (TOKENS / NUM_GROUPS) + mt * BM) * IN_F;
    const float* Bg = W + (size_t)(g * OUT_F + nt * BN) * IN_F;

    // acc[i][j]: m16 tile i (4), n8 tile j (8)
    float acc[4][8][4];
    #pragma unroll
    for (int i = 0; i < 4; ++i)
        #pragma unroll
        for (int j = 0; j < 8; ++j)
            #pragma unroll
            for (int r = 0; r < 4; ++r) acc[i][j][r] = 0.0f;

    // ldmatrix base offsets (k8 slice ks applied by XOR with ks*32; k bits
    // [5:6] are disjoint from base low bits and the swizzle source bits).
    uint32_t a_off[4];
    #pragma unroll
    for (int i = 0; i < 4; ++i)
        a_off[i] = swz((uint32_t)(
            (warp_m * 64 + i * 16 + (lane & 15)) * 128 + (lane & 16)));
    uint32_t b_off[2][2];   // [32-col half][kc half]
    #pragma unroll
    for (int h = 0; h < 2; ++h) {
        b_off[h][0] = swz((uint32_t)((warp_n * 64 + h * 32 + lane) * 128));
        b_off[h][1] = swz((uint32_t)((warp_n * 64 + h * 32 + lane) * 128 + 16));
    }

    // Prologue: fill first STAGES-1 stages
    load_stage(sb, 0, Ag, Bg, 0, tid);
    cp_commit();
    load_stage(sb, 1, Ag, Bg, BK, tid);
    cp_commit();

    for (int kit = 0; kit < KITERS; ++kit) {
        if (kit < KITERS - 1) cp_wait<1>(); else cp_wait<0>();
        __syncthreads();

        if (kit + 2 < KITERS) {
            load_stage(sb, (kit + 2) % STAGES, Ag, Bg, (kit + 2) * BK, tid);
            cp_commit();
        }

        const uint32_t sA = sb + (kit % STAGES) * STAGE_BYTES;
        const uint32_t sB = sA + A_BYTES;

        #pragma unroll
        for (int ks = 0; ks < 4; ++ks) {          // 4 x k8 steps per BK=32
            const uint32_t kx = (uint32_t)(ks * 32);

            uint32_t a[4][4];
            #pragma unroll
            for (int i = 0; i < 4; ++i)
                ldsm4(a[i], sA + (a_off[i] ^ kx));

            uint32_t b0[2][4], b1[2][4];
            #pragma unroll
            for (int h = 0; h < 2; ++h) {
                ldsm4(b0[h], sB + (b_off[h][0] ^ kx));
                ldsm4(b1[h], sB + (b_off[h][1] ^ kx));
            }

            #pragma unroll
            for (int i = 0; i < 4; ++i)
                #pragma unroll
                for (int j = 0; j < 8; ++j)
                    mma_tf32(acc[i][j], a[i], b0[j >> 2][j & 3], b1[j >> 2][j & 3]);
        }
    }

    // Epilogue: m16n8 C frag: thread holds (r=t/4, c=2*(t%4)) pairs at rows r, r+8
    const int m0 = g * (TOKENS / NUM_GROUPS) + mt * BM + warp_m * 64;
    const int n0 = nt * BN + warp_n * 64;
    #pragma unroll
    for (int i = 0; i < 4; ++i) {
        const int r = m0 + i * 16 + (lane >> 2);
        float* p0 = out + (size_t)r * OUT_F + n0 + 2 * (lane & 3);
        float* p1 = p0 + (size_t)8 * OUT_F;
        #pragma unroll
        for (int j = 0; j < 8; ++j) {
            *reinterpret_cast<float2*>(p0 + j * 8) =
                make_float2(acc[i][j][0], acc[i][j][1]);
            *reinterpret_cast<float2*>(p1 + j * 8) =
                make_float2(acc[i][j][2], acc[i][j][3]);
        }
    }
}

// ---------------------------------------------------------------------------
// Host launch
// ---------------------------------------------------------------------------
extern "C" void kernel_launch(void* const* d_in, const int* in_sizes, int n_in,
                              void* d_out, int out_size) {
    const float* x = (const float*)d_in[0];   // [16384, 2048]
    const float* w = (const float*)d_in[1];   // [8, 2048, 2048]
    float* out = (float*)d_out;               // [16384, 2048]

    float* xr = nullptr;
    float* wr = nullptr;
    cudaGetSymbolAddress((void**)&xr, g_xr);
    cudaGetSymbolAddress((void**)&wr, g_wr);

    static bool attr_set = false;
    if (!attr_set) {
        cudaFuncSetAttribute(grouped_gemm_tf32,
                             cudaFuncAttributeMaxDynamicSharedMemorySize,
                             SMEM_TOTAL);
        attr_set = true;
    }

    // Pre-pass: round-to-nearest tf32 copies (X and W)
    const int n4 = (TOKENS * IN_F) / 4;       // 8,388,608 float4 per tensor
    round_tf32_kernel<<<(n4 + 255) / 256, 256>>>((const float4*)x, (float4*)xr, n4);
    round_tf32_kernel<<<(n4 + 255) / 256, 256>>>((const float4*)w, (float4*)wr, n4);

    const int grid = NUM_GROUPS * (TOKENS / NUM_GROUPS / BM) * (OUT_F / BN); // 2048
    grouped_gemm_tf32<<<grid, THREADS, SMEM_TOTAL>>>(xr, wr, out);
}

// round 6
// speedup vs baseline: 1.0746x; 1.0306x over previous
#include <cuda_runtime.h>
#include <cstdint>

// ---------------------------------------------------------------------------
// GroupedLinear: out[t, o] = sum_i X[t, i] * W[g(t), o, i]
// G=8 balanced groups, 2048 tokens/group, in=out=2048, fp32.
//
// R5 analysis: GEMM at ~64% of tensor floor; leak = ldmatrix->MMA latency
// exposure at ks boundaries + post-barrier LDSM burst. This round:
//  (1) fuse the two tf32-round pre-pass launches into one kernel
//      (saves ~8us AND moves the GEMM back under the ncu capture window);
//  (2) explicit register double-buffering of A/B fragments across ks steps;
//  (3) first frag load issued before the cp.async burst each kit.
// ---------------------------------------------------------------------------

#define NUM_GROUPS 8
#define IN_F       2048
#define OUT_F      2048
#define TOKENS     16384

// Pre-rounded tf32 copies (device-global scratch: allowed)
__device__ float g_xr[(size_t)TOKENS * IN_F];                 // 128 MB
__device__ float g_wr[(size_t)NUM_GROUPS * OUT_F * IN_F];     // 128 MB

constexpr int BM = 128;
constexpr int BN = 128;
constexpr int BK = 32;                       // 32 fp32 = 128 B rows
constexpr int THREADS = 128;                 // 4 warps: 2 (M) x 2 (N), 64x64 each
constexpr int STAGES = 3;
constexpr int KITERS = IN_F / BK;            // 64
constexpr int A_BYTES = BM * BK * 4;         // 16 KB
constexpr int B_BYTES = BN * BK * 4;         // 16 KB
constexpr int STAGE_BYTES = A_BYTES + B_BYTES;   // 32 KB
constexpr int SMEM_TOTAL = STAGES * STAGE_BYTES; // 96 KB -> 2 CTAs/SM

// ---------------------------------------------------------------------------
// PTX helpers (baseline PTX only — harness ptxas targets plain sm_103)
// ---------------------------------------------------------------------------
__device__ __forceinline__ uint32_t smem_u32(const void* p) {
    uint32_t a;
    asm("{ .reg .u64 t; cvta.to.shared.u64 t, %1; cvt.u32.u64 %0, t; }"
        : "=r"(a) : "l"(p));
    return a;
}

// SW128 swizzle: XOR row bits [9:7] into 16B-chunk bits [6:4]
__device__ __forceinline__ uint32_t swz(uint32_t o) {
    return o ^ ((o >> 3) & 0x70);
}

__device__ __forceinline__ void cp16(uint32_t dst, const void* src) {
    asm volatile("cp.async.cg.shared.global [%0], [%1], 16;"
                 :: "r"(dst), "l"(src));
}
__device__ __forceinline__ void cp_commit() {
    asm volatile("cp.async.commit_group;");
}
template <int N>
__device__ __forceinline__ void cp_wait() {
    asm volatile("cp.async.wait_group %0;" :: "n"(N));
}

__device__ __forceinline__ void ldsm4(uint32_t* r, uint32_t addr) {
    asm volatile("ldmatrix.sync.aligned.m8n8.x4.shared.b16 {%0,%1,%2,%3}, [%4];"
                 : "=r"(r[0]), "=r"(r[1]), "=r"(r[2]), "=r"(r[3]) : "r"(addr));
}

__device__ __forceinline__ void mma_tf32(float* c, const uint32_t* a,
                                         uint32_t b0, uint32_t b1) {
    asm volatile(
        "mma.sync.aligned.m16n8k8.row.col.f32.tf32.tf32.f32 "
        "{%0,%1,%2,%3}, {%4,%5,%6,%7}, {%8,%9}, {%0,%1,%2,%3};"
        : "+f"(c[0]), "+f"(c[1]), "+f"(c[2]), "+f"(c[3])
        : "r"(a[0]), "r"(a[1]), "r"(a[2]), "r"(a[3]), "r"(b0), "r"(b1));
}

// ---------------------------------------------------------------------------
// Pre-pass (single launch, both tensors): fp32 -> RNA-rounded tf32 copy
// ---------------------------------------------------------------------------
constexpr int N4X = (TOKENS * IN_F) / 4;                          // 8,388,608
constexpr int N4W = (NUM_GROUPS * OUT_F * IN_F) / 4;              // 8,388,608

__global__ void __launch_bounds__(256) round_tf32_kernel(
    const float4* __restrict__ x, const float4* __restrict__ w,
    float4* __restrict__ xr, float4* __restrict__ wr) {
    int i = blockIdx.x * blockDim.x + threadIdx.x;
    const float4* in;
    float4* out;
    int idx;
    if (i < N4X) { in = x; out = xr; idx = i; }
    else         { in = w; out = wr; idx = i - N4X; }
    float4 v = in[idx];
    uint4 o;
    asm("cvt.rna.tf32.f32 %0, %1;" : "=r"(o.x) : "f"(v.x));
    asm("cvt.rna.tf32.f32 %0, %1;" : "=r"(o.y) : "f"(v.y));
    asm("cvt.rna.tf32.f32 %0, %1;" : "=r"(o.z) : "f"(v.z));
    asm("cvt.rna.tf32.f32 %0, %1;" : "=r"(o.w) : "f"(v.w));
    reinterpret_cast<uint4*>(out)[idx] = o;
}

// ---------------------------------------------------------------------------
// Stage loader: A (1024 chunks) + B (1024 chunks), 16 x 16B per thread
// ---------------------------------------------------------------------------
__device__ __forceinline__ void load_stage(uint32_t sb, int stage,
                                           const float* __restrict__ Ag,
                                           const float* __restrict__ Bg,
                                           int k0, int tid) {
    const uint32_t sA = sb + stage * STAGE_BYTES;
    const uint32_t sB = sA + A_BYTES;
    #pragma unroll
    for (int i = 0; i < 8; ++i) {                // A: 128 rows x 8 chunks
        const int c   = tid + THREADS * i;
        const int row = c >> 3;
        const int cc  = c & 7;
        const uint32_t d = swz((uint32_t)(row * 128 + cc * 16));
        cp16(sA + d, Ag + (size_t)row * IN_F + k0 + cc * 4);
    }
    #pragma unroll
    for (int i = 0; i < 8; ++i) {                // B: 128 rows x 8 chunks
        const int c   = tid + THREADS * i;
        const int row = c >> 3;
        const int cc  = c & 7;
        const uint32_t d = swz((uint32_t)(row * 128 + cc * 16));
        cp16(sB + d, Bg + (size_t)row * IN_F + k0 + cc * 4);
    }
}

// Fragment loader for one k8 slice (kx = ks*32, applied by XOR)
__device__ __forceinline__ void load_frags(
    uint32_t sA, uint32_t sB, uint32_t kx,
    const uint32_t* a_off, const uint32_t (*b_off)[2],
    uint32_t (*a)[4], uint32_t (*b0)[4], uint32_t (*b1)[4]) {
    #pragma unroll
    for (int i = 0; i < 4; ++i)
        ldsm4(a[i], sA + (a_off[i] ^ kx));
    #pragma unroll
    for (int h = 0; h < 2; ++h) {
        ldsm4(b0[h], sB + (b_off[h][0] ^ kx));
        ldsm4(b1[h], sB + (b_off[h][1] ^ kx));
    }
}

// ---------------------------------------------------------------------------
// Kernel: one 128x128 output tile per CTA, 4 warps, warp tile 64(M) x 64(N).
// Register-double-buffered fragments across the 4 k8 steps of each kit.
// ---------------------------------------------------------------------------
__global__ void __launch_bounds__(THREADS, 2)
grouped_gemm_tf32(const float* __restrict__ X, const float* __restrict__ W,
                  float* __restrict__ out) {
    extern __shared__ __align__(1024) char smem[];
    const uint32_t sb = smem_u32(smem);
    const int tid  = threadIdx.x;
    const int lane = tid & 31;
    const int wid  = tid >> 5;
    const int warp_m = wid & 1;    // 0..1 -> 64-row halves
    const int warp_n = wid >> 1;   // 0..1 -> 64-col halves

    const int b  = blockIdx.x;
    const int g  = b >> 8;
    const int t  = b & 255;
    const int mt = t >> 4;
    const int nt = t & 15;

    const float* Ag = X + (size_t)(g * (TOKENS / NUM_GROUPS) + mt * BM) * IN_F;
    const float* Bg = W + (size_t)(g * OUT_F + nt * BN) * IN_F;

    float acc[4][8][4];
    #pragma unroll
    for (int i = 0; i < 4; ++i)
        #pragma unroll
        for (int j = 0; j < 8; ++j)
            #pragma unroll
            for (int r = 0; r < 4; ++r) acc[i][j][r] = 0.0f;

    uint32_t a_off[4];
    #pragma unroll
    for (int i = 0; i < 4; ++i)
        a_off[i] = swz((uint32_t)(
            (warp_m * 64 + i * 16 + (lane & 15)) * 128 + (lane & 16)));
    uint32_t b_off[2][2];   // [32-col half][kc half]
    #pragma unroll
    for (int h = 0; h < 2; ++h) {
        b_off[h][0] = swz((uint32_t)((warp_n * 64 + h * 32 + lane) * 128));
        b_off[h][1] = swz((uint32_t)((warp_n * 64 + h * 32 + lane) * 128 + 16));
    }

    // Double-buffered fragment registers
    uint32_t a[2][4][4], b0[2][2][4], b1[2][2][4];

    // Prologue: fill first STAGES-1 stages
    load_stage(sb, 0, Ag, Bg, 0, tid);
    cp_commit();
    load_stage(sb, 1, Ag, Bg, BK, tid);
    cp_commit();

    for (int kit = 0; kit < KITERS; ++kit) {
        if (kit < KITERS - 1) cp_wait<1>(); else cp_wait<0>();
        __syncthreads();

        const uint32_t sA = sb + (kit % STAGES) * STAGE_BYTES;
        const uint32_t sB = sA + A_BYTES;

        // Start tensor-operand flow FIRST (ks0 frags), then the LSU burst.
        load_frags(sA, sB, 0, a_off, b_off, a[0], b0[0], b1[0]);

        if (kit + 2 < KITERS) {
            load_stage(sb, (kit + 2) % STAGES, Ag, Bg, (kit + 2) * BK, tid);
            cp_commit();
        }

        #pragma unroll
        for (int ks = 0; ks < 4; ++ks) {
            const int cur = ks & 1;
            if (ks < 3)
                load_frags(sA, sB, (uint32_t)((ks + 1) * 32), a_off, b_off,
                           a[cur ^ 1], b0[cur ^ 1], b1[cur ^ 1]);
            #pragma unroll
            for (int i = 0; i < 4; ++i)
                #pragma unroll
                for (int j = 0; j < 8; ++j)
                    mma_tf32(acc[i][j], a[cur][i],
                             b0[cur][j >> 2][j & 3], b1[cur][j >> 2][j & 3]);
        }
    }

    // Epilogue
    const int m0 = g * (TOKENS / NUM_GROUPS) + mt * BM + warp_m * 64;
    const int n0 = nt * BN + warp_n * 64;
    #pragma unroll
    for (int i = 0; i < 4; ++i) {
        const int r = m0 + i * 16 + (lane >> 2);
        float* p0 = out + (size_t)r * OUT_F + n0 + 2 * (lane & 3);
        float* p1 = p0 + (size_t)8 * OUT_F;
        #pragma unroll
        for (int j = 0; j < 8; ++j) {
            *reinterpret_cast<float2*>(p0 + j * 8) =
                make_float2(acc[i][j][0], acc[i][j][1]);
            *reinterpret_cast<float2*>(p1 + j * 8) =
                make_float2(acc[i][j][2], acc[i][j][3]);
        }
    }
}

// ---------------------------------------------------------------------------
// Host launch
// ---------------------------------------------------------------------------
extern "C" void kernel_launch(void* const* d_in, const int* in_sizes, int n_in,
                              void* d_out, int out_size) {
    const float* x = (const float*)d_in[0];   // [16384, 2048]
    const float* w = (const float*)d_in[1];   // [8, 2048, 2048]
    float* out = (float*)d_out;               // [16384, 2048]

    float* xr = nullptr;
    float* wr = nullptr;
    cudaGetSymbolAddress((void**)&xr, g_xr);
    cudaGetSymbolAddress((void**)&wr, g_wr);

    static bool attr_set = false;
    if (!attr_set) {
        cudaFuncSetAttribute(grouped_gemm_tf32,
                             cudaFuncAttributeMaxDynamicSharedMemorySize,
                             SMEM_TOTAL);
        attr_set = true;
    }

    // Fused pre-pass: one launch rounds both X and W
    const int total4 = N4X + N4W;             // 16,777,216
    round_tf32_kernel<<<total4 / 256, 256>>>(
        (const float4*)x, (const float4*)w, (float4*)xr, (float4*)wr);

    const int grid = NUM_GROUPS * (TOKENS / NUM_GROUPS / BM) * (OUT_F / BN); // 2048
    grouped_gemm_tf32<<<grid, THREADS, SMEM_TOTAL>>>(xr, wr, out);
}